// round 1
// baseline (speedup 1.0000x reference)
#include <cuda_runtime.h>
#include <cuda_bf16.h>
#include <cstdint>
#include <cstddef>

// Problem: B=4, N=256, E=512
// out = x * (1 + F - avg), where per batch:
//   G = X X^T                       (256x256, K=512)
//   S = L( L(G) @ Kw )              (256x256, K=256)  [mask n<=i on input, p<=i on output]
//   T = L( S @ Qw^T )               (256x256, K=256)  [S already masked; mask n<=i on output]
//   F = T @ X                       (256x512, K=256)  [T already masked]
//   avg[i] = x_i . F_i
//
// Upper-triangular tiles of G/S/T are never written: they stay at the
// zero-initialized __device__ globals, and consumers either mask them or
// never read them (k-loop limited to i0+32). Deterministic on every call.

#define BATCH 4
#define NN_   256
#define EE_   512

__device__ __align__(16) float g_G[BATCH * NN_ * NN_];
__device__ __align__(16) float g_S[BATCH * NN_ * NN_];
__device__ __align__(16) float g_T[BATCH * NN_ * NN_];
__device__ __align__(16) float g_F[BATCH * NN_ * EE_];

// Tiled fp32 GEMM: C[i,j] = sum_k A[i,k] * (NT ? B[j,k] : B[k,j])
// Tile: 32 (M) x 64 (N) x 16 (K), 128 threads, 4x4 micro-tile per thread.
// MASK_A   : zero A[i,k] where k > i (tril mask on the k/n axis)
// MASK_C   : zero C[i,j] where j > i
// SKIP_UP  : skip tiles entirely above the diagonal (j0 >= i0+32): no store
// KLIM     : limit k-loop to k < i0+32 (inputs known zero / masked beyond)
template<bool NT, bool MASK_A, bool MASK_C, bool SKIP_UP, bool KLIM>
__global__ __launch_bounds__(128)
void gemm_tile(const float* __restrict__ A, const float* __restrict__ B,
               float* __restrict__ C,
               int K, int lda, int ldb, int ldc,
               size_t sA, size_t sB, size_t sC)
{
    const int i0 = blockIdx.y * 32;
    const int j0 = blockIdx.x * 64;
    if (SKIP_UP && j0 >= i0 + 32) return;

    const int b = blockIdx.z;
    A += (size_t)b * sA;
    B += (size_t)b * sB;
    C += (size_t)b * sC;

    __shared__ float As[16][36];   // k-major: As[k][i]
    __shared__ float Bs[16][68];   // k-major: Bs[k][j]

    const int tid  = threadIdx.x;
    const int row0 = (tid >> 4) * 4;   // 0..28 within 32-row tile
    const int col0 = (tid & 15) * 4;   // 0..60 within 64-col tile

    const int ar = tid >> 2;           // 0..31 : A-load row
    const int ac = (tid & 3) * 4;      // 0,4,8,12 : A-load k offset

    float acc[4][4] = {};

    const int kend = KLIM ? (i0 + 32) : K;

    for (int k0 = 0; k0 < kend; k0 += 16) {
        // ---- load A tile (32 x 16), store k-major (transposed) ----
        {
            float4 v = *(const float4*)&A[(size_t)(i0 + ar) * lda + k0 + ac];
            if (MASK_A) {
                const int i = i0 + ar;
                if (k0 + ac + 0 > i) v.x = 0.f;
                if (k0 + ac + 1 > i) v.y = 0.f;
                if (k0 + ac + 2 > i) v.z = 0.f;
                if (k0 + ac + 3 > i) v.w = 0.f;
            }
            As[ac + 0][ar] = v.x;
            As[ac + 1][ar] = v.y;
            As[ac + 2][ar] = v.z;
            As[ac + 3][ar] = v.w;
        }
        // ---- load B tile ----
        if (NT) {
            // B rows are j, cols are k: transpose into Bs[k][j]
            #pragma unroll
            for (int it = 0; it < 2; it++) {
                const int f  = tid + it * 128;    // 0..255
                const int j  = f >> 2;            // 0..63
                const int kc = (f & 3) * 4;
                float4 v = *(const float4*)&B[(size_t)(j0 + j) * ldb + k0 + kc];
                Bs[kc + 0][j] = v.x;
                Bs[kc + 1][j] = v.y;
                Bs[kc + 2][j] = v.z;
                Bs[kc + 3][j] = v.w;
            }
        } else {
            // B rows are k, cols are j: direct float4 copy
            #pragma unroll
            for (int it = 0; it < 2; it++) {
                const int f  = tid + it * 128;
                const int kr = f >> 4;            // 0..15
                const int jc = (f & 15) * 4;
                float4 v = *(const float4*)&B[(size_t)(k0 + kr) * ldb + j0 + jc];
                *(float4*)&Bs[kr][jc] = v;
            }
        }
        __syncthreads();

        #pragma unroll
        for (int k = 0; k < 16; k++) {
            float4 a  = *(const float4*)&As[k][row0];
            float4 bv = *(const float4*)&Bs[k][col0];
            const float av[4] = {a.x, a.y, a.z, a.w};
            const float bw[4] = {bv.x, bv.y, bv.z, bv.w};
            #pragma unroll
            for (int u = 0; u < 4; u++)
                #pragma unroll
                for (int v = 0; v < 4; v++)
                    acc[u][v] = fmaf(av[u], bw[v], acc[u][v]);
        }
        __syncthreads();
    }

    // ---- store ----
    #pragma unroll
    for (int u = 0; u < 4; u++) {
        const int i = i0 + row0 + u;
        float4 o;
        o.x = acc[u][0]; o.y = acc[u][1]; o.z = acc[u][2]; o.w = acc[u][3];
        if (MASK_C) {
            const int j = j0 + col0;
            if (j + 0 > i) o.x = 0.f;
            if (j + 1 > i) o.y = 0.f;
            if (j + 2 > i) o.z = 0.f;
            if (j + 3 > i) o.w = 0.f;
        }
        *(float4*)&C[(size_t)i * ldc + j0 + col0] = o;
    }
}

// Per (b, i): avg = x_i . F_i ; out = x * (1 + F - avg)
__global__ __launch_bounds__(128)
void epilogue_kernel(const float* __restrict__ X, const float* __restrict__ F,
                     float* __restrict__ out)
{
    const int i = blockIdx.x;
    const int b = blockIdx.y;
    const size_t base = ((size_t)b * NN_ + i) * EE_;
    const int tid = threadIdx.x;     // 128 threads x 4 floats = 512

    float4 x = *(const float4*)&X[base + tid * 4];
    float4 f = *(const float4*)&F[base + tid * 4];

    float s = x.x * f.x + x.y * f.y + x.z * f.z + x.w * f.w;
    #pragma unroll
    for (int o = 16; o; o >>= 1)
        s += __shfl_xor_sync(0xffffffffu, s, o);

    __shared__ float sm[4];
    if ((tid & 31) == 0) sm[tid >> 5] = s;
    __syncthreads();
    const float avg = sm[0] + sm[1] + sm[2] + sm[3];

    float4 o;
    o.x = x.x * (1.f + f.x - avg);
    o.y = x.y * (1.f + f.y - avg);
    o.z = x.z * (1.f + f.z - avg);
    o.w = x.w * (1.f + f.w - avg);
    *(float4*)&out[base + tid * 4] = o;
}

extern "C" void kernel_launch(void* const* d_in, const int* in_sizes, int n_in,
                              void* d_out, int out_size)
{
    const float* X  = (const float*)d_in[0];   // (4,256,512)
    const float* Qw = (const float*)d_in[1];   // (256,256)
    const float* Kw = (const float*)d_in[2];   // (256,256)
    float* out = (float*)d_out;                // (4,256,512)

    float *G, *S, *T, *F;
    cudaGetSymbolAddress((void**)&G, g_G);
    cudaGetSymbolAddress((void**)&S, g_S);
    cudaGetSymbolAddress((void**)&T, g_T);
    cudaGetSymbolAddress((void**)&F, g_F);

    const size_t sX = (size_t)NN_ * EE_;   // 131072
    const size_t sG = (size_t)NN_ * NN_;   // 65536

    dim3 blk(128);

    // K1: G = X X^T          (NT, skip upper tiles, full K=512)
    gemm_tile<true, false, false, true, false>
        <<<dim3(4, 8, BATCH), blk>>>(X, X, G, EE_, EE_, EE_, NN_, sX, sX, sG);

    // K2: S = L( L(G) @ Kw ) (NN, mask A tril, mask C tril, skip upper, k<=i0+32)
    gemm_tile<false, true, true, true, true>
        <<<dim3(4, 8, BATCH), blk>>>(G, Kw, S, NN_, NN_, NN_, NN_, sG, 0, sG);

    // K3: T = L( S @ Qw^T )  (NT, mask C tril, skip upper, k<=i0+32)
    gemm_tile<true, false, true, true, true>
        <<<dim3(4, 8, BATCH), blk>>>(S, Qw, T, NN_, NN_, NN_, NN_, sG, 0, sG);

    // K4: F = T @ X          (NN, k<=i0+32, full output)
    gemm_tile<false, false, false, false, true>
        <<<dim3(8, 8, BATCH), blk>>>(T, X, F, NN_, NN_, EE_, EE_, sG, sX, sX);

    // K5: epilogue
    epilogue_kernel<<<dim3(NN_, BATCH), blk>>>(X, F, out);
}

// round 2
// speedup vs baseline: 1.4945x; 1.4945x over previous
#include <cuda_runtime.h>
#include <cuda_bf16.h>
#include <cstdint>
#include <cstddef>

// B=4, N=256, E=512. Per batch:
//   G = X X^T                    (K=512, split 8x64, parts summed by K2)
//   S = L( L(G) @ Kw )           (K<=i0+64, split 4x64)
//   T = L( S @ Qw^T )            (K<=i0+64, split 4x64)
//   F = T @ X                    (K<=i0+64, split 4x64)
//   avg[i] = x_i . F_i ; out = x * (1 + F - avg)
// Upper-tri / out-of-range part tiles are never written: they stay at the
// zero-initialized __device__ globals, so consumer sums read exact zeros.
// Deterministic on every call (no atomics).

#define BATCH 4
#define NN_   256
#define EE_   512
#define PART_G (BATCH * NN_ * NN_)   // 262144
#define PART_F (BATCH * NN_ * EE_)   // 524288

__device__ __align__(16) float g_G[8 * PART_G];
__device__ __align__(16) float g_S[4 * PART_G];
__device__ __align__(16) float g_T[4 * PART_G];
__device__ __align__(16) float g_F[4 * PART_F];

// 64x64x16-tile fp32 GEMM, 128 threads, 8x4 micro-tile, double-buffered smem.
// C_part[kc][i,j] = sum_{k in chunk kc} Asum[i,k] * (NT ? B[j,k] : B[k,j])
// Asum = sum of ASUM part buffers of A (stride aPart).
// MASK_A: zero A[i,k] for k>i. MASK_C: zero C[i,j] for j>i.
// SKIP_UP: skip tiles with j0 >= i0+64. KLIM: k-range limited to [0, i0+64).
template<bool NT, bool MASK_A, bool MASK_C, bool SKIP_UP, bool KLIM,
         int ASUM, int KS, int KCHUNK>
__global__ __launch_bounds__(128)
void gemm64(const float* __restrict__ A, const float* __restrict__ B,
            float* __restrict__ C, int K, int lda, int ldb, int ldc,
            size_t sA, size_t sB, size_t sC, size_t aPart, size_t cPart)
{
    const int i0 = blockIdx.y * 64;
    const int j0 = blockIdx.x * 64;
    if (SKIP_UP && j0 >= i0 + 64) return;

    const int z  = blockIdx.z;
    const int b  = z / KS;
    const int kc = z - b * KS;
    const int klim = KLIM ? (i0 + 64) : K;
    const int kbeg = kc * KCHUNK;
    const int kend = min(klim, (kc + 1) * KCHUNK);
    if (kbeg >= kend) return;

    A += (size_t)b * sA;
    B += (size_t)b * sB;
    C += (size_t)b * sC + (size_t)kc * cPart;

    __shared__ float As[2][16][68];   // k-major
    __shared__ float Bs[2][16][68];   // k-major

    const int tid  = threadIdx.x;
    const int lr   = tid >> 2;          // 0..31 (A/B-NT load row, +32 for it=1)
    const int lc4  = (tid & 3) << 2;    // 0,4,8,12 (k offset)
    const int bkr  = tid >> 4;          // 0..7 (B-NN load k row, +8 for it=1)
    const int bjc  = (tid & 15) << 2;   // 0..60 (B-NN col)
    const int row0 = (tid >> 4) << 3;   // 0..56
    const int col0 = (tid & 15) << 2;   // 0..60

    float4 ra[2], rb[2];

    auto loadTile = [&](int kg) {
        #pragma unroll
        for (int it = 0; it < 2; it++) {
            const int r = lr + it * 32;
            const size_t off = (size_t)(i0 + r) * lda + (kg + lc4);
            float4 v = *(const float4*)&A[off];
            #pragma unroll
            for (int s = 1; s < ASUM; s++) {
                float4 w = *(const float4*)&A[off + (size_t)s * aPart];
                v.x += w.x; v.y += w.y; v.z += w.z; v.w += w.w;
            }
            if (MASK_A) {
                const int i = i0 + r, k = kg + lc4;
                if (k + 0 > i) v.x = 0.f;
                if (k + 1 > i) v.y = 0.f;
                if (k + 2 > i) v.z = 0.f;
                if (k + 3 > i) v.w = 0.f;
            }
            ra[it] = v;
            if (NT) {
                rb[it] = *(const float4*)&B[(size_t)(j0 + r) * ldb + (kg + lc4)];
            } else {
                const int kr = bkr + it * 8;
                rb[it] = *(const float4*)&B[(size_t)(kg + kr) * ldb + (j0 + bjc)];
            }
        }
    };

    auto stageTile = [&](int buf) {
        #pragma unroll
        for (int it = 0; it < 2; it++) {
            const int r = lr + it * 32;
            As[buf][lc4 + 0][r] = ra[it].x;
            As[buf][lc4 + 1][r] = ra[it].y;
            As[buf][lc4 + 2][r] = ra[it].z;
            As[buf][lc4 + 3][r] = ra[it].w;
            if (NT) {
                Bs[buf][lc4 + 0][r] = rb[it].x;
                Bs[buf][lc4 + 1][r] = rb[it].y;
                Bs[buf][lc4 + 2][r] = rb[it].z;
                Bs[buf][lc4 + 3][r] = rb[it].w;
            } else {
                const int kr = bkr + it * 8;
                *(float4*)&Bs[buf][kr][bjc] = rb[it];
            }
        }
    };

    float acc[8][4] = {};

    loadTile(kbeg);
    stageTile(0);
    __syncthreads();

    const int nt = (kend - kbeg) >> 4;
    int buf = 0;
    for (int t = 0; t < nt; t++) {
        const bool more = (t + 1) < nt;
        if (more) loadTile(kbeg + (t + 1) * 16);

        #pragma unroll
        for (int k = 0; k < 16; k++) {
            float4 a0 = *(const float4*)&As[buf][k][row0];
            float4 a1 = *(const float4*)&As[buf][k][row0 + 4];
            float4 bv = *(const float4*)&Bs[buf][k][col0];
            const float av[8] = {a0.x, a0.y, a0.z, a0.w, a1.x, a1.y, a1.z, a1.w};
            const float bw[4] = {bv.x, bv.y, bv.z, bv.w};
            #pragma unroll
            for (int u = 0; u < 8; u++)
                #pragma unroll
                for (int v = 0; v < 4; v++)
                    acc[u][v] = fmaf(av[u], bw[v], acc[u][v]);
        }

        if (more) {
            stageTile(buf ^ 1);
            __syncthreads();
            buf ^= 1;
        }
    }

    #pragma unroll
    for (int u = 0; u < 8; u++) {
        const int i = i0 + row0 + u;
        float4 o = make_float4(acc[u][0], acc[u][1], acc[u][2], acc[u][3]);
        if (MASK_C) {
            const int j = j0 + col0;
            if (j + 0 > i) o.x = 0.f;
            if (j + 1 > i) o.y = 0.f;
            if (j + 2 > i) o.z = 0.f;
            if (j + 3 > i) o.w = 0.f;
        }
        *(float4*)&C[(size_t)i * ldc + (j0 + col0)] = o;
    }
}

// Per (b,i): f = sum of 4 F parts; avg = x_i . f_i; out = x*(1+f-avg)
__global__ __launch_bounds__(128)
void epilogue_kernel(const float* __restrict__ X, const float* __restrict__ F,
                     float* __restrict__ out)
{
    const int i = blockIdx.x;
    const int b = blockIdx.y;
    const size_t base = ((size_t)b * NN_ + i) * EE_;
    const int tid = threadIdx.x;           // 128 threads x 4 floats = 512

    float4 x = *(const float4*)&X[base + tid * 4];
    float4 f = make_float4(0.f, 0.f, 0.f, 0.f);
    #pragma unroll
    for (int s = 0; s < 4; s++) {
        float4 w = *(const float4*)&F[(size_t)s * PART_F + base + tid * 4];
        f.x += w.x; f.y += w.y; f.z += w.z; f.w += w.w;
    }

    float s = x.x * f.x + x.y * f.y + x.z * f.z + x.w * f.w;
    #pragma unroll
    for (int o = 16; o; o >>= 1)
        s += __shfl_xor_sync(0xffffffffu, s, o);

    __shared__ float sm[4];
    if ((tid & 31) == 0) sm[tid >> 5] = s;
    __syncthreads();
    const float avg = sm[0] + sm[1] + sm[2] + sm[3];

    float4 o;
    o.x = x.x * (1.f + f.x - avg);
    o.y = x.y * (1.f + f.y - avg);
    o.z = x.z * (1.f + f.z - avg);
    o.w = x.w * (1.f + f.w - avg);
    *(float4*)&out[base + tid * 4] = o;
}

extern "C" void kernel_launch(void* const* d_in, const int* in_sizes, int n_in,
                              void* d_out, int out_size)
{
    const float* X  = (const float*)d_in[0];   // (4,256,512)
    const float* Qw = (const float*)d_in[1];   // (256,256)
    const float* Kw = (const float*)d_in[2];   // (256,256)
    float* out = (float*)d_out;                // (4,256,512)

    float *G, *S, *T, *F;
    cudaGetSymbolAddress((void**)&G, g_G);
    cudaGetSymbolAddress((void**)&S, g_S);
    cudaGetSymbolAddress((void**)&T, g_T);
    cudaGetSymbolAddress((void**)&F, g_F);

    const size_t sX = (size_t)NN_ * EE_;   // 131072
    const size_t sG = (size_t)NN_ * NN_;   // 65536
    dim3 blk(128);

    // K1: G(8 parts) = X X^T   (NT, skip upper, K=512 split 8x64)
    gemm64<true, false, false, true, false, 1, 8, 64>
        <<<dim3(4, 4, 32), blk>>>(X, X, G, EE_, EE_, EE_, NN_,
                                  sX, sX, sG, 0, PART_G);

    // K2: S(4 parts) = L( L(sum G) @ Kw )   (NN, maskA, maskC, skip, klim, sum 8)
    gemm64<false, true, true, true, true, 8, 4, 64>
        <<<dim3(4, 4, 16), blk>>>(G, Kw, S, NN_, NN_, NN_, NN_,
                                  sG, 0, sG, PART_G, PART_G);

    // K3: T(4 parts) = L( (sum S) @ Qw^T )  (NT, maskC, skip, klim, sum 4)
    gemm64<true, false, true, true, true, 4, 4, 64>
        <<<dim3(4, 4, 16), blk>>>(S, Qw, T, NN_, NN_, NN_, NN_,
                                  sG, 0, sG, PART_G, PART_G);

    // K4: F(4 parts) = (sum T) @ X          (NN, klim, sum 4, full output)
    gemm64<false, false, false, false, true, 4, 4, 64>
        <<<dim3(8, 4, 16), blk>>>(T, X, F, NN_, NN_, EE_, EE_,
                                  sG, sX, sX, PART_G, PART_F);

    // K5: epilogue (sums 4 F parts)
    epilogue_kernel<<<dim3(NN_, BATCH), blk>>>(X, F, out);
}

// round 3
// speedup vs baseline: 1.5764x; 1.0548x over previous
#include <cuda_runtime.h>
#include <cuda_bf16.h>
#include <cstdint>
#include <cstddef>

// B=4, N=256, E=512. One persistent kernel, 148 CTAs x 128 threads, 5 phases
// separated by software grid barriers (all 148 CTAs co-resident: 1 CTA/SM min).
//   P1: G parts   G_kc = X X^T (K=512 split 8x64), lower tiles only
//   P2: S parts   S = L( L(sum G) @ Kw )  (K<=i0+64, 4x64 parts)
//   P3: T parts   T = L( (sum S) @ Qw^T )
//   P4: F parts   F = (sum T) @ X
//   P5: out = x * (1 + f - x.f),  f = sum F parts
// Unwritten upper-tri / out-of-range part tiles stay at .bss zeros (never
// written by any launch), so consumer part-sums read exact zeros.
// Deterministic: static job assignment, no data-path atomics.

#define BATCH 4
#define NN_   256
#define EE_   512
#define GRID  148
#define PART_G (BATCH * NN_ * NN_)   // 262144 floats
#define PART_F (BATCH * NN_ * EE_)   // 524288 floats

__device__ __align__(16) float g_G[8 * PART_G];
__device__ __align__(16) float g_S[4 * PART_G];
__device__ __align__(16) float g_T[4 * PART_G];
__device__ __align__(16) float g_F[4 * PART_F];

__device__ unsigned bar_cnt[8];
__device__ unsigned bar_gen[8];

typedef unsigned long long ULL;

__device__ __forceinline__ ULL pack2(float x) {
    ULL r;
    asm("mov.b64 %0, {%1, %1};" : "=l"(r) : "r"(__float_as_uint(x)));
    return r;
}
__device__ __forceinline__ void fma2(ULL& d, ULL a, ULL b) {
    asm("fma.rn.f32x2 %0, %1, %2, %0;" : "+l"(d) : "l"(a), "l"(b));
}
__device__ __forceinline__ float2 unpk(ULL v) {
    unsigned a, b;
    asm("mov.b64 {%0, %1}, %2;" : "=r"(a), "=r"(b) : "l"(v));
    return make_float2(__uint_as_float(a), __uint_as_float(b));
}

// Grid barrier: counting arrive + monotonic generation (replay-safe).
__device__ __forceinline__ void grid_barrier(int idx) {
    __syncthreads();
    if (threadIdx.x == 0) {
        volatile unsigned* genp = &bar_gen[idx];
        const unsigned g = *genp;
        __threadfence();
        if (atomicAdd(&bar_cnt[idx], 1u) == GRID - 1) {
            atomicExch(&bar_cnt[idx], 0u);
            __threadfence();
            atomicAdd(&bar_gen[idx], 1u);
        } else {
            while (*genp == g) { }
        }
        __threadfence();
    }
    __syncthreads();
}

// One 64x64 output tile, K-range [kbeg, kbeg+64), f32x2 micro-kernel.
// A (row-major lda) summed over ASUM part buffers (stride aPart).
// MASK_A: zero A[i,k] for k > i.  MASK_C: zero C[i,j] for j > i.
// NT: B indexed as B[j,k] (ldb = k-stride of row j), else B[k,j].
template<bool NT, bool MASK_A, bool MASK_C, int ASUM>
__device__ __forceinline__ void tile_gemm(
    const float* __restrict__ A, const float* __restrict__ B,
    float* __restrict__ C, int lda, int ldb, int ldc,
    int i0, int j0, int kbeg, size_t aPart,
    float (*As)[16][68], float (*Bs)[16][68])
{
    const int tid  = threadIdx.x;
    const int lr   = tid >> 2;          // 0..31 (+32 on it=1)
    const int lc4  = (tid & 3) << 2;    // 0,4,8,12
    const int bkr  = tid >> 4;          // 0..7 (+8 on it=1)
    const int bjc  = (tid & 15) << 2;   // 0..60
    const int row0 = (tid >> 4) << 3;   // 0..56
    const int col0 = (tid & 15) << 2;   // 0..60

    float4 ra[2], rb[2];

    auto loadT = [&](int kg) {
        #pragma unroll
        for (int it = 0; it < 2; it++) {
            const int r = lr + it * 32;
            const size_t off = (size_t)(i0 + r) * lda + (kg + lc4);
            float4 v = *(const float4*)&A[off];
            #pragma unroll
            for (int s = 1; s < ASUM; s++) {
                float4 w = *(const float4*)&A[off + (size_t)s * aPart];
                v.x += w.x; v.y += w.y; v.z += w.z; v.w += w.w;
            }
            if (MASK_A) {
                const int i = i0 + r, k = kg + lc4;
                if (k + 0 > i) v.x = 0.f;
                if (k + 1 > i) v.y = 0.f;
                if (k + 2 > i) v.z = 0.f;
                if (k + 3 > i) v.w = 0.f;
            }
            ra[it] = v;
            if (NT) {
                rb[it] = *(const float4*)&B[(size_t)(j0 + r) * ldb + (kg + lc4)];
            } else {
                const int kr = bkr + it * 8;
                rb[it] = *(const float4*)&B[(size_t)(kg + kr) * ldb + (j0 + bjc)];
            }
        }
    };

    auto stageT = [&](int buf) {
        #pragma unroll
        for (int it = 0; it < 2; it++) {
            const int r = lr + it * 32;
            As[buf][lc4 + 0][r] = ra[it].x;
            As[buf][lc4 + 1][r] = ra[it].y;
            As[buf][lc4 + 2][r] = ra[it].z;
            As[buf][lc4 + 3][r] = ra[it].w;
            if (NT) {
                Bs[buf][lc4 + 0][r] = rb[it].x;
                Bs[buf][lc4 + 1][r] = rb[it].y;
                Bs[buf][lc4 + 2][r] = rb[it].z;
                Bs[buf][lc4 + 3][r] = rb[it].w;
            } else {
                const int kr = bkr + it * 8;
                *(float4*)&Bs[buf][kr][bjc] = rb[it];
            }
        }
    };

    ULL acc[4][4] = {};   // [row-pair][col], 8 rows x 4 cols

    loadT(kbeg);
    stageT(0);
    __syncthreads();

    int buf = 0;
    #pragma unroll 1
    for (int t = 0; t < 4; t++) {
        if (t < 3) loadT(kbeg + (t + 1) * 16);

        #pragma unroll
        for (int k = 0; k < 16; k++) {
            ulonglong2 aA = *(const ulonglong2*)&As[buf][k][row0];
            ulonglong2 aB = *(const ulonglong2*)&As[buf][k][row0 + 4];
            float4 bv = *(const float4*)&Bs[buf][k][col0];
            const ULL a[4] = {aA.x, aA.y, aB.x, aB.y};
            const ULL b[4] = {pack2(bv.x), pack2(bv.y), pack2(bv.z), pack2(bv.w)};
            #pragma unroll
            for (int u = 0; u < 4; u++)
                #pragma unroll
                for (int v = 0; v < 4; v++)
                    fma2(acc[u][v], a[u], b[v]);
        }

        if (t < 3) {
            stageT(buf ^ 1);
            __syncthreads();
            buf ^= 1;
        }
    }

    #pragma unroll
    for (int u = 0; u < 4; u++) {
        float2 c0 = unpk(acc[u][0]);
        float2 c1 = unpk(acc[u][1]);
        float2 c2 = unpk(acc[u][2]);
        float2 c3 = unpk(acc[u][3]);
        #pragma unroll
        for (int h = 0; h < 2; h++) {
            const int i = i0 + row0 + 2 * u + h;
            float4 o = h ? make_float4(c0.y, c1.y, c2.y, c3.y)
                         : make_float4(c0.x, c1.x, c2.x, c3.x);
            if (MASK_C) {
                const int j = j0 + col0;
                if (j + 0 > i) o.x = 0.f;
                if (j + 1 > i) o.y = 0.f;
                if (j + 2 > i) o.z = 0.f;
                if (j + 3 > i) o.w = 0.f;
            }
            *(float4*)&C[(size_t)i * ldc + (j0 + col0)] = o;
        }
    }
    __syncthreads();   // protect smem reuse by next job
}

__constant__ int tri_r[10] = {0,1,1,2,2,2,3,3,3,3};
__constant__ int tri_c[10] = {0,0,1,0,1,2,0,1,2,3};

__global__ __launch_bounds__(128, 1)
void replicator_fused(const float* __restrict__ X,
                      const float* __restrict__ Qw,
                      const float* __restrict__ Kw,
                      float* __restrict__ out)
{
    __shared__ float As[2][16][68];
    __shared__ float Bs[2][16][68];
    __shared__ float red[4];

    const size_t sX = (size_t)NN_ * EE_;   // 131072
    const size_t sG = (size_t)NN_ * NN_;   // 65536
    const int tid = threadIdx.x;

    // ---- P1: G parts = X X^T, lower tiles, K=512 in 8x64 chunks (320 jobs)
    for (int job = blockIdx.x; job < 320; job += GRID) {
        const int b  = job / 80;
        const int rm = job - b * 80;
        const int kc = rm & 7;
        const int t  = rm >> 3;
        const int i0 = tri_r[t] * 64, j0 = tri_c[t] * 64;
        tile_gemm<true, false, false, 1>(
            X + b * sX, X + b * sX, g_G + (size_t)kc * PART_G + b * sG,
            EE_, EE_, NN_, i0, j0, kc * 64, 0, As, Bs);
    }
    grid_barrier(0);

    // ---- P2: S parts = L( L(sum8 G) @ Kw ), 120 jobs
    for (int job = blockIdx.x; job < 120; job += GRID) {
        const int b  = job / 30;
        const int rm = job - b * 30;
        const int r  = (rm < 1) ? 0 : (rm < 5) ? 1 : (rm < 14) ? 2 : 3;
        const int off = (r == 0) ? 0 : (r == 1) ? 1 : (r == 2) ? 5 : 14;
        const int rem2 = rm - off;
        const int c  = rem2 / (r + 1);
        const int kc = rem2 - c * (r + 1);
        tile_gemm<false, true, true, 8>(
            g_G + b * sG, Kw, g_S + (size_t)kc * PART_G + b * sG,
            NN_, NN_, NN_, r * 64, c * 64, kc * 64, PART_G, As, Bs);
    }
    grid_barrier(1);

    // ---- P3: T parts = L( (sum4 S) @ Qw^T ), 120 jobs
    for (int job = blockIdx.x; job < 120; job += GRID) {
        const int b  = job / 30;
        const int rm = job - b * 30;
        const int r  = (rm < 1) ? 0 : (rm < 5) ? 1 : (rm < 14) ? 2 : 3;
        const int off = (r == 0) ? 0 : (r == 1) ? 1 : (r == 2) ? 5 : 14;
        const int rem2 = rm - off;
        const int c  = rem2 / (r + 1);
        const int kc = rem2 - c * (r + 1);
        tile_gemm<true, false, true, 4>(
            g_S + b * sG, Qw, g_T + (size_t)kc * PART_G + b * sG,
            NN_, NN_, NN_, r * 64, c * 64, kc * 64, PART_G, As, Bs);
    }
    grid_barrier(2);

    // ---- P4: F parts = (sum4 T) @ X, 320 jobs
    for (int job = blockIdx.x; job < 320; job += GRID) {
        const int b  = job / 80;
        const int rm = job - b * 80;
        const int r  = (rm < 8) ? 0 : (rm < 24) ? 1 : (rm < 48) ? 2 : 3;
        const int off = (r == 0) ? 0 : (r == 1) ? 8 : (r == 2) ? 24 : 48;
        const int rem2 = rm - off;
        const int jt = rem2 / (r + 1);
        const int kc = rem2 - jt * (r + 1);
        tile_gemm<false, false, false, 4>(
            g_T + b * sG, X + b * sX, g_F + (size_t)kc * PART_F + b * sX,
            NN_, EE_, EE_, r * 64, jt * 64, kc * 64, PART_G, As, Bs);
    }
    grid_barrier(3);

    // ---- P5: epilogue, 1024 (b,i) rows
    for (int job = blockIdx.x; job < BATCH * NN_; job += GRID) {
        const int b = job >> 8;
        const int i = job & 255;
        const size_t base = ((size_t)b * NN_ + i) * EE_;

        float4 x = *(const float4*)&X[base + tid * 4];
        float4 f = make_float4(0.f, 0.f, 0.f, 0.f);
        #pragma unroll
        for (int s = 0; s < 4; s++) {
            float4 w = *(const float4*)&g_F[(size_t)s * PART_F + base + tid * 4];
            f.x += w.x; f.y += w.y; f.z += w.z; f.w += w.w;
        }

        float sum = x.x * f.x + x.y * f.y + x.z * f.z + x.w * f.w;
        #pragma unroll
        for (int o = 16; o; o >>= 1)
            sum += __shfl_xor_sync(0xffffffffu, sum, o);

        if ((tid & 31) == 0) red[tid >> 5] = sum;
        __syncthreads();
        const float avg = red[0] + red[1] + red[2] + red[3];

        float4 o;
        o.x = x.x * (1.f + f.x - avg);
        o.y = x.y * (1.f + f.y - avg);
        o.z = x.z * (1.f + f.z - avg);
        o.w = x.w * (1.f + f.w - avg);
        *(float4*)&out[base + tid * 4] = o;
        __syncthreads();
    }
}

extern "C" void kernel_launch(void* const* d_in, const int* in_sizes, int n_in,
                              void* d_out, int out_size)
{
    const float* X  = (const float*)d_in[0];   // (4,256,512)
    const float* Qw = (const float*)d_in[1];   // (256,256)
    const float* Kw = (const float*)d_in[2];   // (256,256)
    float* out = (float*)d_out;                // (4,256,512)

    replicator_fused<<<GRID, 128>>>(X, Qw, Kw, out);
}

// round 4
// speedup vs baseline: 1.6087x; 1.0205x over previous
#include <cuda_runtime.h>
#include <cuda_bf16.h>
#include <cstdint>
#include <cstddef>

// B=4, N=256, E=512. One persistent kernel, 148 CTAs x 256 threads, phases:
//   P1: G parts(4) = X X^T            (K=512 chunk 128; lower 64x128 tiles)
//   P2: S parts(4) = L( L(sumG) Kw )  (K<=i0+64 chunk 64)
//   P3: T parts(4) = L( (sumS) Qw^T )
//   P4: F parts(2) = (sumT) X         (chunk 128)
//   P5: out = x*(1 + f - x.f), f = sum F parts
// Unwritten part tiles stay at .bss zeros (never written by anyone), so
// consumer part-sums read exact zeros. Deterministic static schedule.

#define BATCH 4
#define NN_   256
#define EE_   512
#define GRID  148
#define PART_G (BATCH * NN_ * NN_)   // 262144 floats
#define PART_F (BATCH * NN_ * EE_)   // 524288 floats

__device__ __align__(16) float g_G[4 * PART_G];
__device__ __align__(16) float g_S[4 * PART_G];
__device__ __align__(16) float g_T[4 * PART_G];
__device__ __align__(16) float g_F[2 * PART_F];

__device__ unsigned bar_cnt[8];
__device__ unsigned bar_gen[8];

typedef unsigned long long ULL;

__device__ __forceinline__ ULL pack2(float x) {
    ULL r;
    asm("mov.b64 %0, {%1, %1};" : "=l"(r) : "r"(__float_as_uint(x)));
    return r;
}
__device__ __forceinline__ void fma2(ULL& d, ULL a, ULL b) {
    asm("fma.rn.f32x2 %0, %1, %2, %0;" : "+l"(d) : "l"(a), "l"(b));
}
__device__ __forceinline__ float2 unpk(ULL v) {
    unsigned a, b;
    asm("mov.b64 {%0, %1}, %2;" : "=r"(a), "=r"(b) : "l"(v));
    return make_float2(__uint_as_float(a), __uint_as_float(b));
}

__device__ __forceinline__ void grid_barrier(int idx) {
    __syncthreads();
    if (threadIdx.x == 0) {
        volatile unsigned* genp = &bar_gen[idx];
        const unsigned g = *genp;
        __threadfence();
        if (atomicAdd(&bar_cnt[idx], 1u) == GRID - 1) {
            atomicExch(&bar_cnt[idx], 0u);
            __threadfence();
            atomicAdd(&bar_gen[idx], 1u);
        } else {
            while (*genp == g) { }
        }
        __threadfence();
    }
    __syncthreads();
}

// One 64(M) x 128(N) output tile, K range [kbeg, kbeg + 16*nst).
// A row-major (lda), summed over ASUM part buffers (stride aPart).
// NT: B[j,k] (row j has stride ldb), else B[k,j].
// MASK_A: zero A[i,k] for k>i. MASK_C: zero C[i,j] for j>i.
template<bool NT, bool MASK_A, bool MASK_C, int ASUM>
__device__ __forceinline__ void tile_gemm(
    const float* __restrict__ A, const float* __restrict__ B,
    float* __restrict__ C, int lda, int ldb, int ldc,
    int i0, int j0, int kbeg, int nst, size_t aPart,
    float (*As)[16][68], float (*Bs)[16][132])
{
    const int tid  = threadIdx.x;
    const int ar   = tid >> 2;          // 0..63  A-load row
    const int ac   = (tid & 3) << 2;    // 0,4,8,12
    const int bkr  = tid >> 5;          // 0..7 (+8 it=1)  B-NN k row
    const int bjc  = (tid & 31) << 2;   // 0..124          B-NN col
    const int row0 = (tid >> 5) << 3;   // warp*8 : 0..56
    const int col0 = (tid & 31) << 2;   // 0..124

    float4 ra, rb[2];

    auto loadT = [&](int kg) {
        {
            const size_t off = (size_t)(i0 + ar) * lda + (kg + ac);
            float4 v = *(const float4*)&A[off];
            #pragma unroll
            for (int s = 1; s < ASUM; s++) {
                float4 w = *(const float4*)&A[off + (size_t)s * aPart];
                v.x += w.x; v.y += w.y; v.z += w.z; v.w += w.w;
            }
            if (MASK_A) {
                const int i = i0 + ar, k = kg + ac;
                if (k + 0 > i) v.x = 0.f;
                if (k + 1 > i) v.y = 0.f;
                if (k + 2 > i) v.z = 0.f;
                if (k + 3 > i) v.w = 0.f;
            }
            ra = v;
        }
        #pragma unroll
        for (int it = 0; it < 2; it++) {
            if (NT) {
                const int j  = (tid >> 2) + it * 64;   // 0..127
                rb[it] = *(const float4*)&B[(size_t)(j0 + j) * ldb + (kg + ac)];
            } else {
                const int kr = bkr + it * 8;
                rb[it] = *(const float4*)&B[(size_t)(kg + kr) * ldb + (j0 + bjc)];
            }
        }
    };

    auto stageT = [&](int buf) {
        As[buf][ac + 0][ar] = ra.x;
        As[buf][ac + 1][ar] = ra.y;
        As[buf][ac + 2][ar] = ra.z;
        As[buf][ac + 3][ar] = ra.w;
        #pragma unroll
        for (int it = 0; it < 2; it++) {
            if (NT) {
                const int j = (tid >> 2) + it * 64;
                Bs[buf][ac + 0][j] = rb[it].x;
                Bs[buf][ac + 1][j] = rb[it].y;
                Bs[buf][ac + 2][j] = rb[it].z;
                Bs[buf][ac + 3][j] = rb[it].w;
            } else {
                const int kr = bkr + it * 8;
                *(float4*)&Bs[buf][kr][bjc] = rb[it];
            }
        }
    };

    ULL acc[4][4] = {};   // [row-pair 0..3 -> rows row0+2u(+1)][col 0..3]

    loadT(kbeg);
    stageT(0);
    __syncthreads();

    int buf = 0;
    #pragma unroll 1
    for (int t = 0; t < nst; t++) {
        if (t + 1 < nst) loadT(kbeg + (t + 1) * 16);

        #pragma unroll
        for (int k = 0; k < 16; k++) {
            ulonglong2 aA = *(const ulonglong2*)&As[buf][k][row0];
            ulonglong2 aB = *(const ulonglong2*)&As[buf][k][row0 + 4];
            float4 bv = *(const float4*)&Bs[buf][k][col0];
            const ULL a[4] = {aA.x, aA.y, aB.x, aB.y};
            const ULL b[4] = {pack2(bv.x), pack2(bv.y), pack2(bv.z), pack2(bv.w)};
            #pragma unroll
            for (int u = 0; u < 4; u++)
                #pragma unroll
                for (int v = 0; v < 4; v++)
                    fma2(acc[u][v], a[u], b[v]);
        }

        if (t + 1 < nst) {
            stageT(buf ^ 1);
            __syncthreads();
            buf ^= 1;
        }
    }

    #pragma unroll
    for (int u = 0; u < 4; u++) {
        float2 c0 = unpk(acc[u][0]);
        float2 c1 = unpk(acc[u][1]);
        float2 c2 = unpk(acc[u][2]);
        float2 c3 = unpk(acc[u][3]);
        #pragma unroll
        for (int h = 0; h < 2; h++) {
            const int i = i0 + row0 + 2 * u + h;
            float4 o = h ? make_float4(c0.y, c1.y, c2.y, c3.y)
                         : make_float4(c0.x, c1.x, c2.x, c3.x);
            if (MASK_C) {
                const int j = j0 + col0;
                if (j + 0 > i) o.x = 0.f;
                if (j + 1 > i) o.y = 0.f;
                if (j + 2 > i) o.z = 0.f;
                if (j + 3 > i) o.w = 0.f;
            }
            *(float4*)&C[(size_t)i * ldc + (j0 + col0)] = o;
        }
    }
    __syncthreads();   // smem reuse by next job
}

// P1 tiles (r, c2): 6 lower 64x128 tiles of the 256x256 output
__constant__ int t6_r[6] = {0, 1, 2, 3, 2, 3};
__constant__ int t6_c[6] = {0, 0, 0, 0, 1, 1};
// P2/P3 jobs per batch: (r, c2, kc), 17 entries
__constant__ int p2_r[17] = {0,1,1,2,2,2,3,3,3,3, 2,2,2,3,3,3,3};
__constant__ int p2_c[17] = {0,0,0,0,0,0,0,0,0,0, 1,1,1,1,1,1,1};
__constant__ int p2_k[17] = {0,0,1,0,1,2,0,1,2,3, 0,1,2,0,1,2,3};
// P4 (r, kc) combos, 6 entries (x 4 col-tiles)
__constant__ int p4_r[6] = {0, 1, 2, 2, 3, 3};
__constant__ int p4_k[6] = {0, 0, 0, 1, 0, 1};

__global__ __launch_bounds__(256, 1)
void replicator_fused(const float* __restrict__ X,
                      const float* __restrict__ Qw,
                      const float* __restrict__ Kw,
                      float* __restrict__ out)
{
    __shared__ float As[2][16][68];
    __shared__ float Bs[2][16][132];
    __shared__ float red[8];

    const size_t sX = (size_t)NN_ * EE_;
    const size_t sG = (size_t)NN_ * NN_;
    const int tid = threadIdx.x;

    // ---- P1: 96 jobs (b x 6 tiles x 4 kchunks of 128)
    for (int job = blockIdx.x; job < 96; job += GRID) {
        const int b  = job / 24;
        const int rm = job - b * 24;
        const int t  = rm >> 2;
        const int kc = rm & 3;
        tile_gemm<true, false, false, 1>(
            X + b * sX, X + b * sX, g_G + (size_t)kc * PART_G + b * sG,
            EE_, EE_, NN_, t6_r[t] * 64, t6_c[t] * 128, kc * 128, 8, 0, As, Bs);
    }
    grid_barrier(0);

    // ---- P2: 68 jobs (b x 17), chunk 64
    for (int job = blockIdx.x; job < 68; job += GRID) {
        const int b  = job / 17;
        const int e  = job - b * 17;
        tile_gemm<false, true, true, 4>(
            g_G + b * sG, Kw, g_S + (size_t)p2_k[e] * PART_G + b * sG,
            NN_, NN_, NN_, p2_r[e] * 64, p2_c[e] * 128, p2_k[e] * 64, 4,
            PART_G, As, Bs);
    }
    grid_barrier(1);

    // ---- P3: 68 jobs
    for (int job = blockIdx.x; job < 68; job += GRID) {
        const int b  = job / 17;
        const int e  = job - b * 17;
        tile_gemm<true, false, true, 4>(
            g_S + b * sG, Qw, g_T + (size_t)p2_k[e] * PART_G + b * sG,
            NN_, NN_, NN_, p2_r[e] * 64, p2_c[e] * 128, p2_k[e] * 64, 4,
            PART_G, As, Bs);
    }
    grid_barrier(2);

    // ---- P4: 96 jobs (b x 6 (r,kc) x 4 col-tiles), chunk 128
    for (int job = blockIdx.x; job < 96; job += GRID) {
        const int b  = job / 24;
        const int rm = job - b * 24;
        const int e  = rm >> 2;
        const int c4 = rm & 3;
        const int r  = p4_r[e], kc = p4_k[e];
        const int kbeg = kc * 128;
        const int kend = min((r + 1) * 64, kbeg + 128);
        tile_gemm<false, false, false, 4>(
            g_T + b * sG, X + b * sX, g_F + (size_t)kc * PART_F + b * sX,
            NN_, EE_, EE_, r * 64, c4 * 128, kbeg, (kend - kbeg) >> 4,
            PART_G, As, Bs);
    }
    grid_barrier(3);

    // ---- P5: 512 jobs, 2 rows each (threads 0-127 row0, 128-255 row1)
    const int half = tid >> 7;        // 0 or 1
    const int tr   = tid & 127;
    for (int job = blockIdx.x; job < 512; job += GRID) {
        const int row = job * 2 + half;          // 0..1023 = b*256+i
        const size_t base = (size_t)row * EE_;

        float4 x = *(const float4*)&X[base + tr * 4];
        float4 f0 = *(const float4*)&g_F[base + tr * 4];
        float4 f1 = *(const float4*)&g_F[PART_F + base + tr * 4];
        float4 f = make_float4(f0.x + f1.x, f0.y + f1.y,
                               f0.z + f1.z, f0.w + f1.w);

        float sum = x.x * f.x + x.y * f.y + x.z * f.z + x.w * f.w;
        #pragma unroll
        for (int o = 16; o; o >>= 1)
            sum += __shfl_xor_sync(0xffffffffu, sum, o);

        if ((tid & 31) == 0) red[tid >> 5] = sum;
        __syncthreads();
        const float avg = half ? (red[4] + red[5] + red[6] + red[7])
                               : (red[0] + red[1] + red[2] + red[3]);

        float4 o;
        o.x = x.x * (1.f + f.x - avg);
        o.y = x.y * (1.f + f.y - avg);
        o.z = x.z * (1.f + f.z - avg);
        o.w = x.w * (1.f + f.w - avg);
        *(float4*)&out[base + tr * 4] = o;
        __syncthreads();
    }
}

extern "C" void kernel_launch(void* const* d_in, const int* in_sizes, int n_in,
                              void* d_out, int out_size)
{
    const float* X  = (const float*)d_in[0];   // (4,256,512)
    const float* Qw = (const float*)d_in[1];   // (256,256)
    const float* Kw = (const float*)d_in[2];   // (256,256)
    float* out = (float*)d_out;                // (4,256,512)

    replicator_fused<<<GRID, 256>>>(X, Qw, Kw, out);
}

// round 5
// speedup vs baseline: 1.6746x; 1.0410x over previous
#include <cuda_runtime.h>
#include <cuda_bf16.h>
#include <cstdint>
#include <cstddef>

// B=4, N=256, E=512. Persistent kernel: 296 CTAs (2/SM) x 256 threads.
// Phases (grid barriers between):
//   P1: G parts(16) = X X^T          (kchunk 32, 384 jobs)
//   P2: S parts(8)  = L( L(sumG) Kw ) (kchunk 32, 136 jobs)
//   P3: T parts(8)  = L( (sumS) Qw^T )(kchunk 32, 136 jobs)
//   P4: F parts(8)  = (sumT) X        (kchunk 32, 320 jobs)
//   P5: out = x*(1 + f - x.f), f = sum8 F parts (512 jobs)
// Unwritten part tiles stay at .bss zeros (never written by any job), so
// consumer part-sums read exact zeros. Work stealing: first job static
// (= blockIdx), then atomic tickets; per-phase counters are reset by the
// barrier leader, so every execution (incl. graph replays) runs the same
// job set. Deterministic: jobs write disjoint outputs.

#define BATCH 4
#define NN_   256
#define EE_   512
#define GRID  296
#define PART_G (BATCH * NN_ * NN_)   // 262144 floats
#define PART_F (BATCH * NN_ * EE_)   // 524288 floats

__device__ __align__(16) float g_G[16 * PART_G];
__device__ __align__(16) float g_S[8 * PART_G];
__device__ __align__(16) float g_T[8 * PART_G];
__device__ __align__(16) float g_F[8 * PART_F];

__device__ __align__(128) unsigned bar_cnt[32];   // idx*8 spacing
__device__ __align__(128) unsigned bar_gen[32];
__device__ __align__(128) unsigned job_ctr[8];    // per phase

typedef unsigned long long ULL;

__device__ __forceinline__ ULL pack2(float x) {
    ULL r;
    asm("mov.b64 %0, {%1, %1};" : "=l"(r) : "r"(__float_as_uint(x)));
    return r;
}
__device__ __forceinline__ void fma2(ULL& d, ULL a, ULL b) {
    asm("fma.rn.f32x2 %0, %1, %2, %0;" : "+l"(d) : "l"(a), "l"(b));
}
__device__ __forceinline__ float2 unpk(ULL v) {
    unsigned a, b;
    asm("mov.b64 {%0, %1}, %2;" : "=r"(a), "=r"(b) : "l"(v));
    return make_float2(__uint_as_float(a), __uint_as_float(b));
}

// Grid barrier; leader also resets job counters for later phases:
//   barrier(i) resets job_ctr[i+1]; barrier(3) additionally resets job_ctr[0]
//   (for the next execution / graph replay).
__device__ __forceinline__ void grid_barrier(int idx) {
    __syncthreads();
    if (threadIdx.x == 0) {
        volatile unsigned* genp = &bar_gen[idx * 8];
        const unsigned g = *genp;
        __threadfence();
        if (atomicAdd(&bar_cnt[idx * 8], 1u) == GRID - 1) {
            bar_cnt[idx * 8] = 0;
            job_ctr[idx + 1] = 0;
            if (idx == 3) job_ctr[0] = 0;
            __threadfence();
            atomicAdd(&bar_gen[idx * 8], 1u);
        } else {
            while (*genp == g) { }
        }
        __threadfence();
    }
    __syncthreads();
}

// One 64(M) x 128(N) x 32(K) job (2 stages of 16).
// A row-major (lda), summed over ASUM part buffers (stride PART_G).
// NT: B[j,k] (ldb = row stride), else B[k,j].
// MASK_A: zero A[i,k] for k>i. MASK_C: zero C[i,j] for j>i.
template<bool NT, bool MASK_A, bool MASK_C, int ASUM>
__device__ __forceinline__ void tile_gemm(
    const float* __restrict__ A, const float* __restrict__ B,
    float* __restrict__ C, int lda, int ldb, int ldc,
    int i0, int j0, int kbeg,
    float (*As)[16][68], float (*Bs)[16][132])
{
    const int tid  = threadIdx.x;
    const int ar   = tid >> 2;          // 0..63  A-load row
    const int ac   = (tid & 3) << 2;    // 0,4,8,12
    const int bkr  = tid >> 5;          // 0..7 (+8 it=1)
    const int bjc  = (tid & 31) << 2;   // 0..124
    const int row0 = (tid >> 5) << 3;   // 0..56
    const int col0 = (tid & 31) << 2;   // 0..124

    float4 ra, rb[2];

    auto loadT = [&](int kg) {
        {
            const size_t off = (size_t)(i0 + ar) * lda + (kg + ac);
            float4 v = *(const float4*)&A[off];
            #pragma unroll
            for (int s = 1; s < ASUM; s++) {
                float4 w = *(const float4*)&A[off + (size_t)s * PART_G];
                v.x += w.x; v.y += w.y; v.z += w.z; v.w += w.w;
            }
            if (MASK_A) {
                const int i = i0 + ar, k = kg + ac;
                if (k + 0 > i) v.x = 0.f;
                if (k + 1 > i) v.y = 0.f;
                if (k + 2 > i) v.z = 0.f;
                if (k + 3 > i) v.w = 0.f;
            }
            ra = v;
        }
        #pragma unroll
        for (int it = 0; it < 2; it++) {
            if (NT) {
                const int j = (tid >> 2) + it * 64;
                rb[it] = *(const float4*)&B[(size_t)(j0 + j) * ldb + (kg + ac)];
            } else {
                const int kr = bkr + it * 8;
                rb[it] = *(const float4*)&B[(size_t)(kg + kr) * ldb + (j0 + bjc)];
            }
        }
    };

    auto stageT = [&](int buf) {
        As[buf][ac + 0][ar] = ra.x;
        As[buf][ac + 1][ar] = ra.y;
        As[buf][ac + 2][ar] = ra.z;
        As[buf][ac + 3][ar] = ra.w;
        #pragma unroll
        for (int it = 0; it < 2; it++) {
            if (NT) {
                const int j = (tid >> 2) + it * 64;
                Bs[buf][ac + 0][j] = rb[it].x;
                Bs[buf][ac + 1][j] = rb[it].y;
                Bs[buf][ac + 2][j] = rb[it].z;
                Bs[buf][ac + 3][j] = rb[it].w;
            } else {
                const int kr = bkr + it * 8;
                *(float4*)&Bs[buf][kr][bjc] = rb[it];
            }
        }
    };

    ULL acc[4][4] = {};

    auto compute = [&](int buf) {
        #pragma unroll
        for (int k = 0; k < 16; k++) {
            ulonglong2 aA = *(const ulonglong2*)&As[buf][k][row0];
            ulonglong2 aB = *(const ulonglong2*)&As[buf][k][row0 + 4];
            float4 bv = *(const float4*)&Bs[buf][k][col0];
            const ULL a[4] = {aA.x, aA.y, aB.x, aB.y};
            const ULL b[4] = {pack2(bv.x), pack2(bv.y), pack2(bv.z), pack2(bv.w)};
            #pragma unroll
            for (int u = 0; u < 4; u++)
                #pragma unroll
                for (int v = 0; v < 4; v++)
                    fma2(acc[u][v], a[u], b[v]);
        }
    };

    loadT(kbeg);
    stageT(0);
    __syncthreads();
    loadT(kbeg + 16);
    compute(0);
    stageT(1);
    __syncthreads();
    compute(1);

    #pragma unroll
    for (int u = 0; u < 4; u++) {
        float2 c0 = unpk(acc[u][0]);
        float2 c1 = unpk(acc[u][1]);
        float2 c2 = unpk(acc[u][2]);
        float2 c3 = unpk(acc[u][3]);
        #pragma unroll
        for (int h = 0; h < 2; h++) {
            const int i = i0 + row0 + 2 * u + h;
            float4 o = h ? make_float4(c0.y, c1.y, c2.y, c3.y)
                         : make_float4(c0.x, c1.x, c2.x, c3.x);
            if (MASK_C) {
                const int j = j0 + col0;
                if (j + 0 > i) o.x = 0.f;
                if (j + 1 > i) o.y = 0.f;
                if (j + 2 > i) o.z = 0.f;
                if (j + 3 > i) o.w = 0.f;
            }
            *(float4*)&C[(size_t)i * ldc + (j0 + col0)] = o;
        }
    }
    __syncthreads();   // smem reuse by next job
}

// P1: 6 lower 64x128 tiles of 256x256
__constant__ int t6_r[6] = {0, 1, 2, 2, 3, 3};
__constant__ int t6_c[6] = {0, 0, 0, 1, 0, 1};
// P2/P3: 34 (r, c, kc) entries per batch
__constant__ int p2_r[34] = {0,0, 1,1,1,1, 2,2,2,2,2,2, 2,2,2,2,2,2, 3,3,3,3,3,3,3,3, 3,3,3,3,3,3,3,3};
__constant__ int p2_c[34] = {0,0, 0,0,0,0, 0,0,0,0,0,0, 1,1,1,1,1,1, 0,0,0,0,0,0,0,0, 1,1,1,1,1,1,1,1};
__constant__ int p2_k[34] = {0,1, 0,1,2,3, 0,1,2,3,4,5, 0,1,2,3,4,5, 0,1,2,3,4,5,6,7, 0,1,2,3,4,5,6,7};
// P4: 20 (r, kc) entries
__constant__ int p4_r[20] = {0,0, 1,1,1,1, 2,2,2,2,2,2, 3,3,3,3,3,3,3,3};
__constant__ int p4_k[20] = {0,1, 0,1,2,3, 0,1,2,3,4,5, 0,1,2,3,4,5,6,7};

__global__ __launch_bounds__(256, 2)
void replicator_fused(const float* __restrict__ X,
                      const float* __restrict__ Qw,
                      const float* __restrict__ Kw,
                      float* __restrict__ out)
{
    __shared__ float As[2][16][68];
    __shared__ float Bs[2][16][132];
    __shared__ float red[8];
    __shared__ int next_job;

    const size_t sX = (size_t)NN_ * EE_;
    const size_t sG = (size_t)NN_ * NN_;
    const int tid = threadIdx.x;

    // steal helper: thread 0 pops, broadcast via smem
    auto pop = [&](int phase) -> int {
        __syncthreads();
        if (tid == 0) next_job = GRID + (int)atomicAdd(&job_ctr[phase], 1u);
        __syncthreads();
        return next_job;
    };

    // ---- P1: 384 jobs: b(4) x tile(6) x kc(16 of 32)
    for (int job = blockIdx.x; job < 384; job = pop(0)) {
        const int b  = job / 96;
        const int rm = job - b * 96;
        const int t  = rm >> 4;
        const int kc = rm & 15;
        tile_gemm<true, false, false, 1>(
            X + b * sX, X + b * sX, g_G + (size_t)kc * PART_G + b * sG,
            EE_, EE_, NN_, t6_r[t] * 64, t6_c[t] * 128, kc * 32, As, Bs);
    }
    grid_barrier(0);

    // ---- P2: 136 jobs: b(4) x 34
    for (int job = blockIdx.x; job < 136; job = pop(1)) {
        const int b = job / 34;
        const int e = job - b * 34;
        tile_gemm<false, true, true, 16>(
            g_G + b * sG, Kw, g_S + (size_t)p2_k[e] * PART_G + b * sG,
            NN_, NN_, NN_, p2_r[e] * 64, p2_c[e] * 128, p2_k[e] * 32, As, Bs);
    }
    grid_barrier(1);

    // ---- P3: 136 jobs
    for (int job = blockIdx.x; job < 136; job = pop(2)) {
        const int b = job / 34;
        const int e = job - b * 34;
        tile_gemm<true, false, true, 8>(
            g_S + b * sG, Qw, g_T + (size_t)p2_k[e] * PART_G + b * sG,
            NN_, NN_, NN_, p2_r[e] * 64, p2_c[e] * 128, p2_k[e] * 32, As, Bs);
    }
    grid_barrier(2);

    // ---- P4: 320 jobs: b(4) x ct(4) x 20
    for (int job = blockIdx.x; job < 320; job = pop(3)) {
        const int b  = job / 80;
        const int rm = job - b * 80;
        const int ct = rm / 20;
        const int e  = rm - ct * 20;
        tile_gemm<false, false, false, 8>(
            g_T + b * sG, X + b * sX, g_F + (size_t)p4_k[e] * PART_F + b * sX,
            NN_, EE_, EE_, p4_r[e] * 64, ct * 128, p4_k[e] * 32, As, Bs);
    }
    grid_barrier(3);

    // ---- P5: 512 jobs, 2 rows each
    const int half = tid >> 7;
    const int tr   = tid & 127;
    for (int job = blockIdx.x; job < 512; job = pop(4)) {
        const int row = job * 2 + half;           // b*256 + i
        const size_t base = (size_t)row * EE_;

        float4 x = *(const float4*)&X[base + tr * 4];
        float4 f = make_float4(0.f, 0.f, 0.f, 0.f);
        #pragma unroll
        for (int s = 0; s < 8; s++) {
            float4 w = *(const float4*)&g_F[(size_t)s * PART_F + base + tr * 4];
            f.x += w.x; f.y += w.y; f.z += w.z; f.w += w.w;
        }

        float sum = x.x * f.x + x.y * f.y + x.z * f.z + x.w * f.w;
        #pragma unroll
        for (int o = 16; o; o >>= 1)
            sum += __shfl_xor_sync(0xffffffffu, sum, o);

        if ((tid & 31) == 0) red[tid >> 5] = sum;
        __syncthreads();
        const float avg = half ? (red[4] + red[5] + red[6] + red[7])
                               : (red[0] + red[1] + red[2] + red[3]);

        float4 o;
        o.x = x.x * (1.f + f.x - avg);
        o.y = x.y * (1.f + f.y - avg);
        o.z = x.z * (1.f + f.z - avg);
        o.w = x.w * (1.f + f.w - avg);
        *(float4*)&out[base + tr * 4] = o;
        __syncthreads();
    }
}

extern "C" void kernel_launch(void* const* d_in, const int* in_sizes, int n_in,
                              void* d_out, int out_size)
{
    const float* X  = (const float*)d_in[0];   // (4,256,512)
    const float* Qw = (const float*)d_in[1];   // (256,256)
    const float* Kw = (const float*)d_in[2];   // (256,256)
    float* out = (float*)d_out;                // (4,256,512)

    replicator_fused<<<GRID, 256>>>(X, Qw, Kw, out);
}

// round 6
// speedup vs baseline: 1.7491x; 1.0445x over previous
#include <cuda_runtime.h>
#include <cuda_bf16.h>
#include <cstdint>
#include <cstddef>

// B=4, N=256, E=512. Persistent kernel: 296 CTAs (2/SM) x 256 threads.
// Static job schedule (job = blockIdx.x + wave*GRID), grid barriers between
// phases:
//   P1: G parts(8) = X X^T             (kchunk 64, 192 jobs)
//   P2: S parts(4) = L( L(sum8 G) Kw ) (kchunk 64,  68 jobs)
//   P3: T parts(4) = L( (sum4 S) Qw^T )(kchunk 64,  68 jobs)
//   P4: F parts(4) = (sum4 T) X        (kchunk 64, 160 jobs)
//   P5: out = x*(1 + f - x.f), f = sum4 F parts (512 jobs)
// Part tiles that no job ever writes stay at .bss zeros, so consumer
// part-sums read exact zeros. Deterministic: fixed job->output map,
// disjoint writes, no data-path atomics.

#define BATCH 4
#define NN_   256
#define EE_   512
#define GRID  296
#define PART_G (BATCH * NN_ * NN_)   // 262144 floats
#define PART_F (BATCH * NN_ * EE_)   // 524288 floats

__device__ __align__(16) float g_G[8 * PART_G];
__device__ __align__(16) float g_S[4 * PART_G];
__device__ __align__(16) float g_T[4 * PART_G];
__device__ __align__(16) float g_F[4 * PART_F];

__device__ __align__(128) unsigned bar_cnt[32];   // idx*8 spacing
__device__ __align__(128) unsigned bar_gen[32];

typedef unsigned long long ULL;

__device__ __forceinline__ ULL pack2(float x) {
    ULL r;
    asm("mov.b64 %0, {%1, %1};" : "=l"(r) : "r"(__float_as_uint(x)));
    return r;
}
__device__ __forceinline__ void fma2(ULL& d, ULL a, ULL b) {
    asm("fma.rn.f32x2 %0, %1, %2, %0;" : "+l"(d) : "l"(a), "l"(b));
}
__device__ __forceinline__ float2 unpk(ULL v) {
    unsigned a, b;
    asm("mov.b64 {%0, %1}, %2;" : "=r"(a), "=r"(b) : "l"(v));
    return make_float2(__uint_as_float(a), __uint_as_float(b));
}

__device__ __forceinline__ void grid_barrier(int idx) {
    __syncthreads();
    if (threadIdx.x == 0) {
        volatile unsigned* genp = &bar_gen[idx * 8];
        const unsigned g = *genp;
        __threadfence();
        if (atomicAdd(&bar_cnt[idx * 8], 1u) == GRID - 1) {
            bar_cnt[idx * 8] = 0;
            __threadfence();
            atomicAdd(&bar_gen[idx * 8], 1u);
        } else {
            while (*genp == g) { }
        }
        __threadfence();
    }
    __syncthreads();
}

// One 64(M) x 128(N) x 64(K) job: 4 double-buffered stages of 16 k.
// A row-major (lda), summed over ASUM part buffers (stride PART_G).
// NT: B[j,k] (ldb = row stride), else B[k,j].
// MASK_A: zero A[i,k] for k>i. MASK_C: zero C[i,j] for j>i.
template<bool NT, bool MASK_A, bool MASK_C, int ASUM>
__device__ __forceinline__ void tile_gemm(
    const float* __restrict__ A, const float* __restrict__ B,
    float* __restrict__ C, int lda, int ldb, int ldc,
    int i0, int j0, int kbeg,
    float (*As)[16][68], float (*Bs)[16][132])
{
    const int tid  = threadIdx.x;
    const int ar   = tid >> 2;          // 0..63  A-load row
    const int ac   = (tid & 3) << 2;    // 0,4,8,12
    const int bkr  = tid >> 5;          // 0..7 (+8 it=1)
    const int bjc  = (tid & 31) << 2;   // 0..124
    const int row0 = (tid >> 5) << 3;   // 0..56
    const int col0 = (tid & 31) << 2;   // 0..124

    float4 ra, rb[2];

    auto loadT = [&](int kg) {
        {
            const size_t off = (size_t)(i0 + ar) * lda + (kg + ac);
            float4 v = *(const float4*)&A[off];
            #pragma unroll
            for (int s = 1; s < ASUM; s++) {
                float4 w = *(const float4*)&A[off + (size_t)s * PART_G];
                v.x += w.x; v.y += w.y; v.z += w.z; v.w += w.w;
            }
            if (MASK_A) {
                const int i = i0 + ar, k = kg + ac;
                if (k + 0 > i) v.x = 0.f;
                if (k + 1 > i) v.y = 0.f;
                if (k + 2 > i) v.z = 0.f;
                if (k + 3 > i) v.w = 0.f;
            }
            ra = v;
        }
        #pragma unroll
        for (int it = 0; it < 2; it++) {
            if (NT) {
                const int j = (tid >> 2) + it * 64;
                rb[it] = *(const float4*)&B[(size_t)(j0 + j) * ldb + (kg + ac)];
            } else {
                const int kr = bkr + it * 8;
                rb[it] = *(const float4*)&B[(size_t)(kg + kr) * ldb + (j0 + bjc)];
            }
        }
    };

    auto stageT = [&](int buf) {
        As[buf][ac + 0][ar] = ra.x;
        As[buf][ac + 1][ar] = ra.y;
        As[buf][ac + 2][ar] = ra.z;
        As[buf][ac + 3][ar] = ra.w;
        #pragma unroll
        for (int it = 0; it < 2; it++) {
            if (NT) {
                const int j = (tid >> 2) + it * 64;
                Bs[buf][ac + 0][j] = rb[it].x;
                Bs[buf][ac + 1][j] = rb[it].y;
                Bs[buf][ac + 2][j] = rb[it].z;
                Bs[buf][ac + 3][j] = rb[it].w;
            } else {
                const int kr = bkr + it * 8;
                *(float4*)&Bs[buf][kr][bjc] = rb[it];
            }
        }
    };

    ULL acc[4][4] = {};

    auto compute = [&](int buf) {
        #pragma unroll
        for (int k = 0; k < 16; k++) {
            ulonglong2 aA = *(const ulonglong2*)&As[buf][k][row0];
            ulonglong2 aB = *(const ulonglong2*)&As[buf][k][row0 + 4];
            float4 bv = *(const float4*)&Bs[buf][k][col0];
            const ULL a[4] = {aA.x, aA.y, aB.x, aB.y};
            const ULL b[4] = {pack2(bv.x), pack2(bv.y), pack2(bv.z), pack2(bv.w)};
            #pragma unroll
            for (int u = 0; u < 4; u++)
                #pragma unroll
                for (int v = 0; v < 4; v++)
                    fma2(acc[u][v], a[u], b[v]);
        }
    };

    // 4 stages, double-buffered
    loadT(kbeg);
    stageT(0);
    __syncthreads();
    loadT(kbeg + 16);
    compute(0);
    stageT(1);
    __syncthreads();
    loadT(kbeg + 32);
    compute(1);
    stageT(0);
    __syncthreads();
    loadT(kbeg + 48);
    compute(0);
    stageT(1);
    __syncthreads();
    compute(1);

    #pragma unroll
    for (int u = 0; u < 4; u++) {
        float2 c0 = unpk(acc[u][0]);
        float2 c1 = unpk(acc[u][1]);
        float2 c2 = unpk(acc[u][2]);
        float2 c3 = unpk(acc[u][3]);
        #pragma unroll
        for (int h = 0; h < 2; h++) {
            const int i = i0 + row0 + 2 * u + h;
            float4 o = h ? make_float4(c0.y, c1.y, c2.y, c3.y)
                         : make_float4(c0.x, c1.x, c2.x, c3.x);
            if (MASK_C) {
                const int j = j0 + col0;
                if (j + 0 > i) o.x = 0.f;
                if (j + 1 > i) o.y = 0.f;
                if (j + 2 > i) o.z = 0.f;
                if (j + 3 > i) o.w = 0.f;
            }
            *(float4*)&C[(size_t)i * ldc + (j0 + col0)] = o;
        }
    }
    __syncthreads();   // smem reuse by next job
}

// P1: 6 lower 64x128 tiles of 256x256
__constant__ int t6_r[6] = {0, 1, 2, 2, 3, 3};
__constant__ int t6_c[6] = {0, 0, 0, 1, 0, 1};
// P2/P3: 17 (r, c, kc64) entries per batch, kc <= r
__constant__ int p2_r[17] = {0, 1,1, 2,2,2, 2,2,2, 3,3,3,3, 3,3,3,3};
__constant__ int p2_c[17] = {0, 0,0, 0,0,0, 1,1,1, 0,0,0,0, 1,1,1,1};
__constant__ int p2_k[17] = {0, 0,1, 0,1,2, 0,1,2, 0,1,2,3, 0,1,2,3};
// P4: 10 (r, kc64) entries, kc <= r
__constant__ int p4_r[10] = {0, 1,1, 2,2,2, 3,3,3,3};
__constant__ int p4_k[10] = {0, 0,1, 0,1,2, 0,1,2,3};

__global__ __launch_bounds__(256, 2)
void replicator_fused(const float* __restrict__ X,
                      const float* __restrict__ Qw,
                      const float* __restrict__ Kw,
                      float* __restrict__ out)
{
    __shared__ float As[2][16][68];
    __shared__ float Bs[2][16][132];
    __shared__ float red[8];

    const size_t sX = (size_t)NN_ * EE_;
    const size_t sG = (size_t)NN_ * NN_;
    const int tid = threadIdx.x;

    // ---- P1: 192 jobs: b(4) x tile(6) x kc(8 of 64)
    for (int job = blockIdx.x; job < 192; job += GRID) {
        const int b  = job / 48;
        const int rm = job - b * 48;
        const int t  = rm >> 3;
        const int kc = rm & 7;
        tile_gemm<true, false, false, 1>(
            X + b * sX, X + b * sX, g_G + (size_t)kc * PART_G + b * sG,
            EE_, EE_, NN_, t6_r[t] * 64, t6_c[t] * 128, kc * 64, As, Bs);
    }
    grid_barrier(0);

    // ---- P2: 68 jobs: b(4) x 17, A = sum8 G, masked
    for (int job = blockIdx.x; job < 68; job += GRID) {
        const int b = job / 17;
        const int e = job - b * 17;
        tile_gemm<false, true, true, 8>(
            g_G + b * sG, Kw, g_S + (size_t)p2_k[e] * PART_G + b * sG,
            NN_, NN_, NN_, p2_r[e] * 64, p2_c[e] * 128, p2_k[e] * 64, As, Bs);
    }
    grid_barrier(1);

    // ---- P3: 68 jobs: A = sum4 S (already tril-masked)
    for (int job = blockIdx.x; job < 68; job += GRID) {
        const int b = job / 17;
        const int e = job - b * 17;
        tile_gemm<true, false, true, 4>(
            g_S + b * sG, Qw, g_T + (size_t)p2_k[e] * PART_G + b * sG,
            NN_, NN_, NN_, p2_r[e] * 64, p2_c[e] * 128, p2_k[e] * 64, As, Bs);
    }
    grid_barrier(2);

    // ---- P4: 160 jobs: b(4) x ct(4) x 10, A = sum4 T
    for (int job = blockIdx.x; job < 160; job += GRID) {
        const int b  = job / 40;
        const int rm = job - b * 40;
        const int ct = rm / 10;
        const int e  = rm - ct * 10;
        tile_gemm<false, false, false, 4>(
            g_T + b * sG, X + b * sX, g_F + (size_t)p4_k[e] * PART_F + b * sX,
            NN_, EE_, EE_, p4_r[e] * 64, ct * 128, p4_k[e] * 64, As, Bs);
    }
    grid_barrier(3);

    // ---- P5: 512 jobs, 2 rows each (thread halves)
    const int half = tid >> 7;
    const int tr   = tid & 127;
    for (int job = blockIdx.x; job < 512; job += GRID) {
        const int row = job * 2 + half;           // b*256 + i
        const size_t base = (size_t)row * EE_;

        float4 x = *(const float4*)&X[base + tr * 4];
        float4 f = make_float4(0.f, 0.f, 0.f, 0.f);
        #pragma unroll
        for (int s = 0; s < 4; s++) {
            float4 w = *(const float4*)&g_F[(size_t)s * PART_F + base + tr * 4];
            f.x += w.x; f.y += w.y; f.z += w.z; f.w += w.w;
        }

        float sum = x.x * f.x + x.y * f.y + x.z * f.z + x.w * f.w;
        #pragma unroll
        for (int o = 16; o; o >>= 1)
            sum += __shfl_xor_sync(0xffffffffu, sum, o);

        if ((tid & 31) == 0) red[tid >> 5] = sum;
        __syncthreads();
        const float avg = half ? (red[4] + red[5] + red[6] + red[7])
                               : (red[0] + red[1] + red[2] + red[3]);

        float4 o;
        o.x = x.x * (1.f + f.x - avg);
        o.y = x.y * (1.f + f.y - avg);
        o.z = x.z * (1.f + f.z - avg);
        o.w = x.w * (1.f + f.w - avg);
        *(float4*)&out[base + tr * 4] = o;
        __syncthreads();
    }
}

extern "C" void kernel_launch(void* const* d_in, const int* in_sizes, int n_in,
                              void* d_out, int out_size)
{
    const float* X  = (const float*)d_in[0];   // (4,256,512)
    const float* Qw = (const float*)d_in[1];   // (256,256)
    const float* Kw = (const float*)d_in[2];   // (256,256)
    float* out = (float*)d_out;                // (4,256,512)

    replicator_fused<<<GRID, 256>>>(X, Qw, Kw, out);
}